// round 4
// baseline (speedup 1.0000x reference)
#include <cuda_runtime.h>

// DotAttention: rnn_out [S,B,H] f32, state [2,2,B,H/2] f32 -> out [B,H,1] f32
// S=2048, B=32, H=1024.
// pass1: flash-style online-softmax partials. 4-warp CTAs, merged vector in
//        smem (low regs -> 6 CTAs/SM), 108 variable s-ranges per batch so the
//        whole grid (864 CTAs) fits in one wave on 148 SMs.
// pass2: fused combine (M/L) + weighted sum of partial accumulators.

#define S_LEN 2048
#define B_DIM 32
#define H_DIM 1024
#define RPB   108                       // s-ranges per batch (divisible by 4)
#define NPART (B_DIM * RPB)             // 3456 partials

__device__ float g_m[NPART];
__device__ float g_l[NPART];
__device__ float g_acc[(size_t)NPART * H_DIM];   // ~14.2 MB scratch

__global__ __launch_bounds__(128, 6) void pass1(const float* __restrict__ rnn,
                                                const float* __restrict__ state) {
    __shared__ float4 s_mrg[H_DIM / 4];          // 4 KB merged[b,:]
    const int tid  = threadIdx.x;
    const int lane = tid & 31;
    const int wid  = tid >> 5;                   // 0..3
    const int b    = blockIdx.x / (RPB / 4);
    const int quad = blockIdx.x % (RPB / 4);

    // cooperative load of merged[b,:] (256 float4, 128 threads -> 2 each)
#pragma unroll
    for (int k = 0; k < 2; k++) {
        int idx = tid + k * 128;
        int h = idx * 4;
        int d = h >> 9;
        int hh = h & 511;
        s_mrg[idx] = *reinterpret_cast<const float4*>(
            state + (size_t)(2 + d) * B_DIM * 512 + (size_t)b * 512 + hh);
    }
    __syncthreads();

    const int r  = quad * 4 + wid;               // 0..107
    const int s0 = (r * S_LEN) / RPB;
    const int s1 = ((r + 1) * S_LEN) / RPB;

    float4 acc[8];
#pragma unroll
    for (int j = 0; j < 8; j++) acc[j] = make_float4(0.f, 0.f, 0.f, 0.f);
    float m = -1e30f, l = 0.f;

    const float* base = rnn + (size_t)s0 * (B_DIM * H_DIM) + (size_t)b * H_DIM;

    for (int s = s0; s < s1; s++, base += B_DIM * H_DIM) {
        const float4* row = reinterpret_cast<const float4*>(base);
        float4 x[8];
#pragma unroll
        for (int j = 0; j < 8; j++) x[j] = row[j * 32 + lane];

        float p = 0.f;
#pragma unroll
        for (int j = 0; j < 8; j++) {
            float4 g = s_mrg[j * 32 + lane];
            p += x[j].x * g.x + x[j].y * g.y + x[j].z * g.z + x[j].w * g.w;
        }
#pragma unroll
        for (int off = 16; off > 0; off >>= 1)
            p += __shfl_xor_sync(0xffffffffu, p, off);

        float mnew  = fmaxf(m, p);
        float scale = __expf(m - mnew);
        float w     = __expf(p - mnew);
#pragma unroll
        for (int j = 0; j < 8; j++) {
            acc[j].x = acc[j].x * scale + w * x[j].x;
            acc[j].y = acc[j].y * scale + w * x[j].y;
            acc[j].z = acc[j].z * scale + w * x[j].z;
            acc[j].w = acc[j].w * scale + w * x[j].w;
        }
        l = l * scale + w;
        m = mnew;
    }

    const int part = b * RPB + r;
    float4* out4 = reinterpret_cast<float4*>(g_acc + (size_t)part * H_DIM);
#pragma unroll
    for (int j = 0; j < 8; j++) out4[j * 32 + lane] = acc[j];
    if (lane == 0) {
        g_m[part] = m;
        g_l[part] = l;
    }
}

// Fused combine + weighted sum. grid = (16 h-slices, 32 batches), 256 threads.
__global__ __launch_bounds__(256) void pass2(float* __restrict__ out) {
    const int slice = blockIdx.x;        // 0..15
    const int b     = blockIdx.y;        // 0..31
    const int tid   = threadIdx.x;
    const int lane  = tid & 31;
    const int wid   = tid >> 5;

    __shared__ float sw[RPB];
    __shared__ float s_red[8];

    // ---- normalized chunk weights (threads 0..RPB-1 own one chunk) ----
    float mm = -1e30f, ll = 0.f;
    if (tid < RPB) {
        mm = g_m[b * RPB + tid];
        ll = g_l[b * RPB + tid];
    }
    float v = mm;
#pragma unroll
    for (int off = 16; off > 0; off >>= 1)
        v = fmaxf(v, __shfl_xor_sync(0xffffffffu, v, off));
    if (lane == 0) s_red[wid] = v;
    __syncthreads();
    float M = s_red[0];
#pragma unroll
    for (int k = 1; k < 8; k++) M = fmaxf(M, s_red[k]);
    __syncthreads();

    float e  = (tid < RPB) ? __expf(mm - M) : 0.f;
    float le = ll * e;
#pragma unroll
    for (int off = 16; off > 0; off >>= 1)
        le += __shfl_xor_sync(0xffffffffu, le, off);
    if (lane == 0) s_red[wid] = le;
    __syncthreads();
    float L = 0.f;
#pragma unroll
    for (int k = 0; k < 8; k++) L += s_red[k];
    if (tid < RPB) sw[tid] = e / L;
    __syncthreads();

    // ---- weighted sum over RPB chunks for 64 h values ----
    const int hq = tid & 15;             // 16 float4 = 64 floats per slice
    const int cg = tid >> 4;             // 16 groups

    const float* bse = g_acc + ((size_t)b * RPB) * H_DIM + slice * 64 + hq * 4;

    float rx = 0.f, ry = 0.f, rz = 0.f, rw = 0.f;
#pragma unroll
    for (int k = 0; k < 7; k++) {        // 7*16 = 112 >= 108
        int chunk = k * 16 + cg;
        if (chunk < RPB) {
            float4 a = *reinterpret_cast<const float4*>(bse + (size_t)chunk * H_DIM);
            float w = sw[chunk];
            rx += w * a.x; ry += w * a.y; rz += w * a.z; rw += w * a.w;
        }
    }

    __shared__ float4 red[256];
    red[tid] = make_float4(rx, ry, rz, rw);
    __syncthreads();
#pragma unroll
    for (int st = 8; st > 0; st >>= 1) {
        if (cg < st) {
            float4 o = red[tid + 16 * st];
            rx += o.x; ry += o.y; rz += o.z; rw += o.w;
            red[tid] = make_float4(rx, ry, rz, rw);
        }
        __syncthreads();
    }

    if (cg == 0) {
        reinterpret_cast<float4*>(out)[(b * H_DIM + slice * 64) / 4 + hq] =
            make_float4(rx, ry, rz, rw);
    }
}

extern "C" void kernel_launch(void* const* d_in, const int* in_sizes, int n_in,
                              void* d_out, int out_size) {
    const float* rnn   = (const float*)d_in[0];
    const float* state = (const float*)d_in[1];
    float* out         = (float*)d_out;

    pass1<<<B_DIM * (RPB / 4), 128>>>(rnn, state);
    dim3 g2(16, B_DIM);
    pass2<<<g2, 256>>>(out);
}

// round 5
// speedup vs baseline: 1.3282x; 1.3282x over previous
#include <cuda_runtime.h>

// DotAttention: rnn_out [S,B,H] f32, state [2,2,B,H/2] f32 -> out [B,H,1] f32
// S=2048, B=32, H=1024.
// pass1: flash-style online-softmax partials; one warp per (b, 32-row chunk),
//        merged vector register-resident (R2 structure). grid=256 CTAs =
//        exactly one wave at 2 CTAs/SM on 148 SMs.
// pass2: fused combine (M/L) + weighted sum of partial accumulators.

#define S_LEN 2048
#define B_DIM 32
#define H_DIM 1024
#define SPLIT 64
#define CHUNK (S_LEN / SPLIT)          // 32 rows per warp
#define WARPS_PER_CTA 8
#define NPART (B_DIM * SPLIT)          // 2048 partials

__device__ float g_m[NPART];
__device__ float g_l[NPART];
__device__ float g_acc[(size_t)NPART * H_DIM];   // 8.4 MB scratch (L2-resident)

__global__ __launch_bounds__(256) void pass1(const float* __restrict__ rnn,
                                             const float* __restrict__ state) {
    const int warp = blockIdx.x * WARPS_PER_CTA + (threadIdx.x >> 5);
    const int lane = threadIdx.x & 31;
    const int b = warp / SPLIT;
    const int chunk = warp % SPLIT;

    // merged[b, h]: h = j*128 + lane*4; direction = h>>9
    float4 mrg[8];
#pragma unroll
    for (int j = 0; j < 8; j++) {
        int h = j * 128 + lane * 4;
        int d = h >> 9;
        int hh = h & 511;
        mrg[j] = *reinterpret_cast<const float4*>(
            state + (size_t)(2 + d) * B_DIM * 512 + (size_t)b * 512 + hh);
    }

    float4 acc[8];
#pragma unroll
    for (int j = 0; j < 8; j++) acc[j] = make_float4(0.f, 0.f, 0.f, 0.f);
    float m = -1e30f, l = 0.f;

    const float* base = rnn + (size_t)(chunk * CHUNK) * (B_DIM * H_DIM)
                            + (size_t)b * H_DIM;

    for (int s = 0; s < CHUNK; s++) {
        const float4* row =
            reinterpret_cast<const float4*>(base + (size_t)s * (B_DIM * H_DIM));
        float4 x[8];
#pragma unroll
        for (int j = 0; j < 8; j++) x[j] = row[j * 32 + lane];

        float p = 0.f;
#pragma unroll
        for (int j = 0; j < 8; j++) {
            p += x[j].x * mrg[j].x + x[j].y * mrg[j].y +
                 x[j].z * mrg[j].z + x[j].w * mrg[j].w;
        }
#pragma unroll
        for (int off = 16; off > 0; off >>= 1)
            p += __shfl_xor_sync(0xffffffffu, p, off);

        float mnew  = fmaxf(m, p);
        float scale = __expf(m - mnew);
        float w     = __expf(p - mnew);
#pragma unroll
        for (int j = 0; j < 8; j++) {
            acc[j].x = acc[j].x * scale + w * x[j].x;
            acc[j].y = acc[j].y * scale + w * x[j].y;
            acc[j].z = acc[j].z * scale + w * x[j].z;
            acc[j].w = acc[j].w * scale + w * x[j].w;
        }
        l = l * scale + w;
        m = mnew;
    }

    float4* out4 = reinterpret_cast<float4*>(g_acc + (size_t)warp * H_DIM);
#pragma unroll
    for (int j = 0; j < 8; j++) out4[j * 32 + lane] = acc[j];
    if (lane == 0) {
        g_m[warp] = m;
        g_l[warp] = l;
    }
}

// Fused combine + weighted sum. grid = (16 h-slices, 32 batches), 256 threads.
__global__ __launch_bounds__(256) void pass2(float* __restrict__ out) {
    const int slice = blockIdx.x;        // 0..15
    const int b     = blockIdx.y;        // 0..31
    const int tid   = threadIdx.x;
    const int lane  = tid & 31;
    const int wid   = tid >> 5;

    __shared__ float sw[SPLIT];
    __shared__ float s_red[8];

    // ---- normalized chunk weights (threads 0..SPLIT-1 own one chunk) ----
    float mm = -1e30f, ll = 0.f;
    if (tid < SPLIT) {
        mm = g_m[b * SPLIT + tid];
        ll = g_l[b * SPLIT + tid];
    }
    float v = mm;
#pragma unroll
    for (int off = 16; off > 0; off >>= 1)
        v = fmaxf(v, __shfl_xor_sync(0xffffffffu, v, off));
    if (lane == 0) s_red[wid] = v;
    __syncthreads();
    float M = s_red[0];
#pragma unroll
    for (int k = 1; k < 8; k++) M = fmaxf(M, s_red[k]);
    __syncthreads();

    float e  = (tid < SPLIT) ? __expf(mm - M) : 0.f;
    float le = ll * e;
#pragma unroll
    for (int off = 16; off > 0; off >>= 1)
        le += __shfl_xor_sync(0xffffffffu, le, off);
    if (lane == 0) s_red[wid] = le;
    __syncthreads();
    float L = 0.f;
#pragma unroll
    for (int k = 0; k < 8; k++) L += s_red[k];
    if (tid < SPLIT) sw[tid] = e / L;
    __syncthreads();

    // ---- weighted sum over SPLIT chunks for 64 h values ----
    const int hq = tid & 15;             // 16 float4 = 64 floats per slice
    const int cg = tid >> 4;             // 16 groups x 4 chunks

    const float* bse = g_acc + ((size_t)b * SPLIT) * H_DIM + slice * 64 + hq * 4;

    float rx = 0.f, ry = 0.f, rz = 0.f, rw = 0.f;
#pragma unroll
    for (int k = 0; k < 4; k++) {
        int chunk = k * 16 + cg;
        float4 a = *reinterpret_cast<const float4*>(bse + (size_t)chunk * H_DIM);
        float w = sw[chunk];
        rx += w * a.x; ry += w * a.y; rz += w * a.z; rw += w * a.w;
    }

    __shared__ float4 red[256];
    red[tid] = make_float4(rx, ry, rz, rw);
    __syncthreads();
#pragma unroll
    for (int st = 8; st > 0; st >>= 1) {
        if (cg < st) {
            float4 o = red[tid + 16 * st];
            rx += o.x; ry += o.y; rz += o.z; rw += o.w;
            red[tid] = make_float4(rx, ry, rz, rw);
        }
        __syncthreads();
    }

    if (cg == 0) {
        reinterpret_cast<float4*>(out)[(b * H_DIM + slice * 64) / 4 + hq] =
            make_float4(rx, ry, rz, rw);
    }
}

extern "C" void kernel_launch(void* const* d_in, const int* in_sizes, int n_in,
                              void* d_out, int out_size) {
    const float* rnn   = (const float*)d_in[0];
    const float* state = (const float*)d_in[1];
    float* out         = (float*)d_out;

    pass1<<<NPART / WARPS_PER_CTA, 256>>>(rnn, state);
    dim3 g2(16, B_DIM);
    pass2<<<g2, 256>>>(out);
}